// round 3
// baseline (speedup 1.0000x reference)
#include <cuda_runtime.h>
#include <math.h>

#define B_ 8
#define N_ 2048
#define K_ 4
#define CB 512
#define PP 8
#define S_ 2
#define TMK 128
#define TNK 128

typedef unsigned long long ull;

#define FFMA2(d,a,b) asm("fma.rn.f32x2 %0, %1, %2, %0;" : "+l"(d) : "l"(a), "l"(b))
__device__ __forceinline__ ull pack2(float lo, float hi) {
    ull r; asm("mov.b64 %0, {%1,%2};" : "=l"(r) : "f"(lo), "f"(hi)); return r;
}
__device__ __forceinline__ float2 unpack2(ull v) {
    float2 f; asm("mov.b64 {%0,%1}, %2;" : "=f"(f.x), "=f"(f.y) : "l"(v)); return f;
}

// top-4 insertion, strict > (stable: earlier-inserted wins ties)
__device__ __forceinline__ void ins4(float (&v)[4], int (&ix)[4], float p, int m) {
    if (p > v[3]) {
        if (p > v[1]) {
            if (p > v[0]) { v[3]=v[2];ix[3]=ix[2]; v[2]=v[1];ix[2]=ix[1]; v[1]=v[0];ix[1]=ix[0]; v[0]=p;ix[0]=m; }
            else          { v[3]=v[2];ix[3]=ix[2]; v[2]=v[1];ix[2]=ix[1]; v[1]=p;ix[1]=m; }
        } else {
            if (p > v[2]) { v[3]=v[2];ix[3]=ix[2]; v[2]=p;ix[2]=m; }
            else          { v[3]=p;ix[3]=m; }
        }
    }
}
__device__ __forceinline__ bool lexgt(float pv, int pi, float qv, int qi) {
    return (pv > qv) || (pv == qv && pi < qi);
}
// top-4 insertion, lexicographic (val desc, idx asc) — order-independent
__device__ __forceinline__ void ins4lex(float (&v)[4], int (&ix)[4], float p, int m) {
    if (lexgt(p, m, v[3], ix[3])) {
        if (lexgt(p, m, v[1], ix[1])) {
            if (lexgt(p, m, v[0], ix[0])) { v[3]=v[2];ix[3]=ix[2]; v[2]=v[1];ix[2]=ix[1]; v[1]=v[0];ix[1]=ix[0]; v[0]=p;ix[0]=m; }
            else                          { v[3]=v[2];ix[3]=ix[2]; v[2]=v[1];ix[2]=ix[1]; v[1]=p;ix[1]=m; }
        } else {
            if (lexgt(p, m, v[2], ix[2])) { v[3]=v[2];ix[3]=ix[2]; v[2]=p;ix[2]=m; }
            else                          { v[3]=p;ix[3]=m; }
        }
    }
}

// ---------------- scratch ----------------
__device__ float  g_xcn[(size_t)B_*CB*N_];   // [B][C][N]
__device__ float  g_xnc[(size_t)B_*N_*CB];   // [B][N][C]
__device__ float4 g_x0nc[(size_t)B_*N_];     // input [B][N][4]
__device__ float  g_xx[(size_t)B_*N_];
__device__ float4 g_cv4[(size_t)B_*N_*S_];
__device__ int4   g_ci4[(size_t)B_*N_*S_];
__device__ int4   g_idx4[(size_t)B_*N_];
__device__ float  g_uv[(size_t)B_*N_*512];   // UV per stage; y5 for conv5
__device__ float  g_mx[(size_t)B_*N_*256];
__device__ float  g_mn[(size_t)B_*N_*256];
__device__ float  g_sum[5*512];
__device__ float  g_ssq[5*512];
__device__ float4 g_wT4[90112];              // packed [c4][O2] per stage

// ---------------- prep: pack weights combined [c4][2O] + clear stats ----------------
__global__ void k_prep_w_all(const float* __restrict__ w1, const float* __restrict__ w2,
                             const float* __restrict__ w3, const float* __restrict__ w4,
                             const float* __restrict__ w5) {
    int t = blockIdx.x*blockDim.x + threadIdx.x;
    if (t < 5*512) { g_sum[t] = 0.f; g_ssq[t] = 0.f; }
    if (t >= 88192) return;
    const float* w; int realC, O, parts, lt;
    if      (t < 128)   { w = w1; realC = 3;   O = 64;  parts = 2; lt = t; }
    else if (t < 2176)  { w = w2; realC = 64;  O = 64;  parts = 2; lt = t - 128; }
    else if (t < 6272)  { w = w3; realC = 64;  O = 128; parts = 2; lt = t - 2176; }
    else if (t < 22656) { w = w4; realC = 128; O = 256; parts = 2; lt = t - 6272; }
    else                { w = w5; realC = 512; O = 512; parts = 1; lt = t - 22656; }
    int O2 = parts * O;
    int o2 = lt % O2; int c4 = lt / O2;
    int part = (o2 >= O) ? 1 : 0; int oc = o2 - part*O;
    float4 v; float* pv = (float*)&v;
    #pragma unroll
    for (int j = 0; j < 4; j++) {
        int c = c4*4 + j;
        pv[j] = (c < realC) ? w[oc*(parts*realC) + part*realC + c] : 0.f;
    }
    g_wT4[t] = v;
}

__global__ void k_prep_x0(const float* __restrict__ x) {
    int t = blockIdx.x*blockDim.x + threadIdx.x;
    if (t >= B_*N_) return;
    int b = t >> 11, n = t & (N_-1);
    float vx = x[(b*3+0)*N_ + n];
    float vy = x[(b*3+1)*N_ + n];
    float vz = x[(b*3+2)*N_ + n];
    g_x0nc[t] = make_float4(vx, vy, vz, 0.f);
    g_xx[t] = vx*vx + vy*vy + vz*vz;
}

// ---------------- knn: distance GEMM with register top-4 ----------------
template<int C>
__global__ void __launch_bounds__(256) k_knn3(const float* __restrict__ base, long bstride) {
    constexpr int KCc = (C < 16) ? 4 : 16;
    constexpr int CP = (C + KCc - 1) / KCc * KCc;
    __shared__ float Ash[KCc*TMK];
    __shared__ ull   Bsh[KCc*TNK];
    __shared__ float xxs[TNK];
    const int b  = blockIdx.z;
    const int s  = blockIdx.y;
    const int n0 = blockIdx.x * TMK;
    const float* X = base + (long)b * bstride;
    const float* xxg = g_xx + b*N_;
    const int tid = threadIdx.x;
    const int ty = tid >> 3;   // 0..31 -> 4 rows each
    const int tx = tid & 7;    // 0..7  -> 16 cols each
    const int r0 = ty*4, c0 = tx*16;

    float xxr[4];
    #pragma unroll
    for (int i = 0; i < 4; i++) xxr[i] = xxg[n0 + r0 + i];

    float cv[4][4]; int ci[4][4];
    #pragma unroll
    for (int r = 0; r < 4; r++)
        #pragma unroll
        for (int q = 0; q < 4; q++) { cv[r][q] = -3.4e38f; ci[r][q] = 0; }

    for (int mb = 0; mb < (N_/S_)/TNK; mb++) {
        const int m0 = s*(N_/S_) + mb*TNK;
        if (tid < TNK) xxs[tid] = xxg[m0 + tid];
        ull acc0[16], acc1[16];
        #pragma unroll
        for (int j = 0; j < 16; j++) { acc0[j] = 0ull; acc1[j] = 0ull; }

        for (int kc = 0; kc < CP; kc += KCc) {
            #pragma unroll
            for (int t = tid; t < KCc*TMK; t += 256) {
                int c = t >> 7, r = t & (TMK-1);
                Ash[t] = (kc + c < C) ? X[(long)(kc+c)*N_ + n0 + r] : 0.f;
            }
            #pragma unroll
            for (int t = tid; t < KCc*TNK; t += 256) {
                int c = t >> 7, m = t & (TNK-1);
                float v = (kc + c < C) ? X[(long)(kc+c)*N_ + m0 + m] : 0.f;
                Bsh[t] = pack2(v, v);
            }
            __syncthreads();
            #pragma unroll
            for (int cc = 0; cc < KCc; cc++) {
                ulonglong2 a01 = *(const ulonglong2*)&Ash[cc*TMK + r0];
                const ulonglong2* bp = (const ulonglong2*)&Bsh[cc*TNK + c0];
                #pragma unroll
                for (int u = 0; u < 8; u++) {
                    ulonglong2 bb = bp[u];
                    FFMA2(acc0[2*u],   a01.x, bb.x);
                    FFMA2(acc0[2*u+1], a01.x, bb.y);
                    FFMA2(acc1[2*u],   a01.y, bb.x);
                    FFMA2(acc1[2*u+1], a01.y, bb.y);
                }
            }
            __syncthreads();
        }
        // consume accumulators into register top-4 (column order ascending)
        #pragma unroll
        for (int j = 0; j < 16; j++) {
            float xc = xxs[c0 + j];
            int col = m0 + c0 + j;
            float2 va = unpack2(acc0[j]);
            ins4(cv[0], ci[0], 2.f*va.x - xxr[0] - xc, col);
            ins4(cv[1], ci[1], 2.f*va.y - xxr[1] - xc, col);
            float2 vb = unpack2(acc1[j]);
            ins4(cv[2], ci[2], 2.f*vb.x - xxr[2] - xc, col);
            ins4(cv[3], ci[3], 2.f*vb.y - xxr[3] - xc, col);
        }
        __syncthreads();
    }
    // butterfly merge across the 8 column-lanes (lex comparator: order-independent)
    #pragma unroll
    for (int st = 1; st <= 4; st <<= 1) {
        #pragma unroll
        for (int r = 0; r < 4; r++) {
            float pv[4]; int pi[4];
            #pragma unroll
            for (int q = 0; q < 4; q++) {
                pv[q] = __shfl_xor_sync(0xffffffffu, cv[r][q], st);
                pi[q] = __shfl_xor_sync(0xffffffffu, ci[r][q], st);
            }
            #pragma unroll
            for (int q = 0; q < 4; q++) ins4lex(cv[r], ci[r], pv[q], pi[q]);
        }
    }
    if (tx == 0) {
        #pragma unroll
        for (int r = 0; r < 4; r++) {
            int o = (b*N_ + n0 + r0 + r)*S_ + s;
            g_cv4[o] = make_float4(cv[r][0], cv[r][1], cv[r][2], cv[r][3]);
            g_ci4[o] = make_int4(ci[r][0], ci[r][1], ci[r][2], ci[r][3]);
        }
    }
}

// ---------------- merge split candidates -> final knn idx ----------------
__global__ void k_merge() {
    int t = blockIdx.x*blockDim.x + threadIdx.x;
    if (t >= B_*N_) return;
    float cv[4] = {-3.4e38f,-3.4e38f,-3.4e38f,-3.4e38f};
    int ci[4] = {0,0,0,0};
    #pragma unroll
    for (int s2 = 0; s2 < S_; s2++) {
        float4 v = g_cv4[t*S_ + s2];
        int4   i = g_ci4[t*S_ + s2];
        ins4lex(cv, ci, v.x, i.x); ins4lex(cv, ci, v.y, i.y);
        ins4lex(cv, ci, v.z, i.z); ins4lex(cv, ci, v.w, i.w);
    }
    g_idx4[t] = make_int4(ci[0], ci[1], ci[2], ci[3]);
}

// ---------------- generic GEMM: out[pt][O2] = src[pt][C] * W[C][O2] ----------------
template<int TN>
__global__ void __launch_bounds__(256) k_gemm(const float* __restrict__ src, int CS, int coff,
                                              int C, int c4n, const float4* __restrict__ wb,
                                              int O2, float* __restrict__ out) {
    constexpr int CT = TN/16;
    __shared__ float Ash[16*132];
    __shared__ ull   Bsh[16*TN];
    const int pt0 = blockIdx.x * 128;
    const int ob0 = blockIdx.y * TN;
    const int tid = threadIdx.x;
    const int ty = tid >> 4, tx = tid & 15;
    const int r0 = ty*8, c0 = tx*CT;

    ull acc[4][CT];
    #pragma unroll
    for (int p = 0; p < 4; p++)
        #pragma unroll
        for (int j = 0; j < CT; j++) acc[p][j] = 0ull;

    const int C16 = (C + 15) & ~15;
    for (int kc = 0; kc < C16; kc += 16) {
        #pragma unroll
        for (int t = tid; t < 16*128; t += 256) {
            int c = t & 15, r = t >> 4;
            float v = (kc + c < C) ? src[(long)(pt0 + r)*CS + coff + kc + c] : 0.f;
            Ash[c*132 + r] = v;
        }
        #pragma unroll
        for (int t = tid; t < 4*TN; t += 256) {
            int q = t / TN, o = t - q*TN;
            int c4 = (kc >> 2) + q;
            float4 w = (c4 < c4n) ? wb[(long)c4*O2 + ob0 + o] : make_float4(0.f,0.f,0.f,0.f);
            Bsh[(4*q+0)*TN + o] = pack2(w.x, w.x);
            Bsh[(4*q+1)*TN + o] = pack2(w.y, w.y);
            Bsh[(4*q+2)*TN + o] = pack2(w.z, w.z);
            Bsh[(4*q+3)*TN + o] = pack2(w.w, w.w);
        }
        __syncthreads();
        #pragma unroll
        for (int cc = 0; cc < 16; cc++) {
            ulonglong2 aA = *(const ulonglong2*)&Ash[cc*132 + r0];
            ulonglong2 aB = *(const ulonglong2*)&Ash[cc*132 + r0 + 4];
            #pragma unroll
            for (int j = 0; j < CT; j++) {
                ull bb = Bsh[cc*TN + c0 + j];
                FFMA2(acc[0][j], aA.x, bb);
                FFMA2(acc[1][j], aA.y, bb);
                FFMA2(acc[2][j], aB.x, bb);
                FFMA2(acc[3][j], aB.y, bb);
            }
        }
        __syncthreads();
    }
    #pragma unroll
    for (int p = 0; p < 4; p++) {
        float lo[CT], hi[CT];
        #pragma unroll
        for (int j = 0; j < CT; j++) {
            float2 u = unpack2(acc[p][j]);
            lo[j] = u.x; hi[j] = u.y;
        }
        long rowL = (long)(pt0 + r0 + 2*p) * O2 + ob0 + c0;
        #pragma unroll
        for (int j4 = 0; j4 < CT/4; j4++) {
            *(float4*)&out[rowL + j4*4]      = make_float4(lo[j4*4], lo[j4*4+1], lo[j4*4+2], lo[j4*4+3]);
            *(float4*)&out[rowL + O2 + j4*4] = make_float4(hi[j4*4], hi[j4*4+1], hi[j4*4+2], hi[j4*4+3]);
        }
    }
}

// ---------------- gather + minmax over k + stats ----------------
__global__ void k_edge_max(const float* __restrict__ uv, int O, int O2, int stage) {
    __shared__ int sidx[PP*K_];
    const int blk = blockIdx.x;
    const int pt0 = blk * PP;
    const int o = threadIdx.x;
    const int b = pt0 >> 11;
    if (o < PP) ((int4*)sidx)[o] = g_idx4[pt0 + o];
    __syncthreads();
    float s1 = 0.f, s2 = 0.f;
    #pragma unroll
    for (int p = 0; p < PP; p++) {
        float v = uv[(long)(pt0 + p)*O2 + O + o];
        float mx = -3.4e38f, mn = 3.4e38f;
        #pragma unroll
        for (int k = 0; k < K_; k++) {
            int nb = sidx[p*K_ + k];
            float u = uv[(long)(b*N_ + nb)*O2 + o];
            float y = u + v;
            mx = fmaxf(mx, y); mn = fminf(mn, y);
            s1 += y; s2 += y*y;
        }
        g_mx[(long)(pt0 + p)*O + o] = mx;
        g_mn[(long)(pt0 + p)*O + o] = mn;
    }
    atomicAdd(&g_sum[stage*512 + o], s1);
    atomicAdd(&g_ssq[stage*512 + o], s2);
}

// ---------------- BN finalize + relu + both layouts + next-stage norms ----------------
__global__ void k_fin_edge(int O, int coff, int stage, const float* __restrict__ gm,
                           const float* __restrict__ bt, float invcnt) {
    __shared__ float red[256];
    const int bn = blockIdx.x;
    const int o  = threadIdx.x;
    const int so = stage*512 + o;
    float mean = g_sum[so] * invcnt;
    float var  = g_ssq[so] * invcnt - mean*mean;
    float a  = gm[o] * rsqrtf(var + 1e-5f);
    float c0 = bt[o] - mean*a;
    long t = (long)bn*O + o;
    float z = (a >= 0.f) ? (a*g_mx[t] + c0) : (a*g_mn[t] + c0);
    z = fmaxf(z, 0.f);
    int b = bn >> 11, n = bn & (N_-1);
    g_xnc[(long)bn*CB + coff + o] = z;
    g_xcn[((long)b*CB + coff + o)*N_ + n] = z;
    red[o] = z*z;
    __syncthreads();
    for (int st = O >> 1; st > 0; st >>= 1) {
        if (o < st) red[o] += red[o + st];
        __syncthreads();
    }
    if (o == 0) g_xx[bn] = red[0];
}

// ---------------- conv5 stats over y5 ----------------
__global__ void __launch_bounds__(512) k_stats5() {
    const int o = threadIdx.x;
    const int p0 = blockIdx.x * 128;
    float s1 = 0.f, s2 = 0.f;
    for (int i = 0; i < 128; i++) {
        float y = g_uv[(long)(p0 + i)*CB + o];
        s1 += y; s2 += y*y;
    }
    atomicAdd(&g_sum[4*512 + o], s1);
    atomicAdd(&g_ssq[4*512 + o], s2);
}

__global__ void k_fin5(const float* __restrict__ gm, const float* __restrict__ bt,
                       float* __restrict__ out) {
    __shared__ float tile[32][33];
    const int b  = blockIdx.z;
    const int o0 = blockIdx.y*32;
    const int n0 = blockIdx.x*32;
    const int tx = threadIdx.x, ty0 = threadIdx.y;
    const float invcnt = 1.f / (float)(B_*N_);
    int o = o0 + tx;
    float mean = g_sum[4*512 + o] * invcnt;
    float var  = g_ssq[4*512 + o] * invcnt - mean*mean;
    float a  = gm[o] * rsqrtf(var + 1e-5f);
    float c0 = bt[o] - mean*a;
    #pragma unroll
    for (int i = 0; i < 4; i++) {
        int ty = ty0 + i*8;
        float y = g_uv[((long)b*N_ + n0 + ty)*CB + o];
        tile[ty][tx] = tanhf(a*y + c0);
    }
    __syncthreads();
    #pragma unroll
    for (int i = 0; i < 4; i++) {
        int ty = ty0 + i*8;
        out[((long)b*CB + o0 + ty)*N_ + n0 + tx] = tile[tx][ty];
    }
}

// ---------------- launch ----------------
extern "C" void kernel_launch(void* const* d_in, const int* in_sizes, int n_in,
                              void* d_out, int out_size) {
    const float* x = (const float*)d_in[0];
    const float* W[5]; const float* G[5]; const float* Bt[5];
    for (int i = 0; i < 5; i++) {
        W[i]  = (const float*)d_in[1 + 3*i];
        G[i]  = (const float*)d_in[2 + 3*i];
        Bt[i] = (const float*)d_in[3 + 3*i];
    }
    float* out = (float*)d_out;

    float* xcn;   cudaGetSymbolAddress((void**)&xcn,  g_xcn);
    float* xnc;   cudaGetSymbolAddress((void**)&xnc,  g_xnc);
    float* x0nc;  cudaGetSymbolAddress((void**)&x0nc, g_x0nc);
    float* uv;    cudaGetSymbolAddress((void**)&uv,   g_uv);
    float4* wt;   cudaGetSymbolAddress((void**)&wt,   g_wT4);

    const float invE = 1.f / (float)(B_*N_*K_);
    const dim3 kg(N_/TMK, S_, B_);
    const int wstart[5] = {0, 128, 2176, 6272, 22656};

    k_prep_w_all<<<(88192 + 255)/256, 256>>>(W[0], W[1], W[2], W[3], W[4]);
    k_prep_x0<<<(B_*N_ + 255)/256, 256>>>(x);

    // stage 0: C=3 -> O=64
    k_knn3<3><<<kg, 256>>>(x, (long)3*N_);
    k_merge<<<B_*N_/256, 256>>>();
    k_gemm<64><<<dim3(128, 2), 256>>>(x0nc, 4, 0, 4, 1, wt + wstart[0], 128, uv);
    k_edge_max<<<B_*N_/PP, 64>>>(uv, 64, 128, 0);
    k_fin_edge<<<B_*N_, 64>>>(64, 0, 0, G[0], Bt[0], invE);
    // stage 1: C=64 -> O=64
    k_knn3<64><<<kg, 256>>>(xcn, (long)CB*N_);
    k_merge<<<B_*N_/256, 256>>>();
    k_gemm<64><<<dim3(128, 2), 256>>>(xnc, CB, 0, 64, 16, wt + wstart[1], 128, uv);
    k_edge_max<<<B_*N_/PP, 64>>>(uv, 64, 128, 1);
    k_fin_edge<<<B_*N_, 64>>>(64, 64, 1, G[1], Bt[1], invE);
    // stage 2: C=64 -> O=128
    k_knn3<64><<<kg, 256>>>(xcn + (long)64*N_, (long)CB*N_);
    k_merge<<<B_*N_/256, 256>>>();
    k_gemm<128><<<dim3(128, 2), 256>>>(xnc, CB, 64, 64, 16, wt + wstart[2], 256, uv);
    k_edge_max<<<B_*N_/PP, 128>>>(uv, 128, 256, 2);
    k_fin_edge<<<B_*N_, 128>>>(128, 128, 2, G[2], Bt[2], invE);
    // stage 3: C=128 -> O=256
    k_knn3<128><<<kg, 256>>>(xcn + (long)128*N_, (long)CB*N_);
    k_merge<<<B_*N_/256, 256>>>();
    k_gemm<128><<<dim3(128, 4), 256>>>(xnc, CB, 128, 128, 32, wt + wstart[3], 512, uv);
    k_edge_max<<<B_*N_/PP, 256>>>(uv, 256, 512, 3);
    k_fin_edge<<<B_*N_, 256>>>(256, 256, 3, G[3], Bt[3], invE);
    // block 5: 512x512
    k_gemm<128><<<dim3(128, 4), 256>>>(xnc, CB, 0, 512, 128, wt + wstart[4], 512, uv);
    k_stats5<<<128, 512>>>();
    k_fin5<<<dim3(N_/32, CB/32, B_), dim3(32, 8)>>>(G[4], Bt[4], out);
}

// round 4
// speedup vs baseline: 3.8070x; 3.8070x over previous
#include <cuda_runtime.h>
#include <math.h>

#define B_ 8
#define N_ 2048
#define K_ 4
#define CB 512
#define PP 8
#define S_ 2
#define TMK 128
#define TNK 128

typedef unsigned long long ull;

#define FFMA2(d,a,b) asm("fma.rn.f32x2 %0, %1, %2, %0;" : "+l"(d) : "l"(a), "l"(b))
__device__ __forceinline__ ull pack2(float lo, float hi) {
    ull r; asm("mov.b64 %0, {%1,%2};" : "=l"(r) : "f"(lo), "f"(hi)); return r;
}
__device__ __forceinline__ float2 unpack2(ull v) {
    float2 f; asm("mov.b64 {%0,%1}, %2;" : "=f"(f.x), "=f"(f.y) : "l"(v)); return f;
}

// top-4 insertion, strict > (stable: earlier-inserted wins ties)
__device__ __forceinline__ void ins4(float (&v)[4], int (&ix)[4], float p, int m) {
    if (p > v[3]) {
        if (p > v[1]) {
            if (p > v[0]) { v[3]=v[2];ix[3]=ix[2]; v[2]=v[1];ix[2]=ix[1]; v[1]=v[0];ix[1]=ix[0]; v[0]=p;ix[0]=m; }
            else          { v[3]=v[2];ix[3]=ix[2]; v[2]=v[1];ix[2]=ix[1]; v[1]=p;ix[1]=m; }
        } else {
            if (p > v[2]) { v[3]=v[2];ix[3]=ix[2]; v[2]=p;ix[2]=m; }
            else          { v[3]=p;ix[3]=m; }
        }
    }
}
__device__ __forceinline__ bool lexgt(float pv, int pi, float qv, int qi) {
    return (pv > qv) || (pv == qv && pi < qi);
}
__device__ __forceinline__ void ins4lex(float (&v)[4], int (&ix)[4], float p, int m) {
    if (lexgt(p, m, v[3], ix[3])) {
        if (lexgt(p, m, v[1], ix[1])) {
            if (lexgt(p, m, v[0], ix[0])) { v[3]=v[2];ix[3]=ix[2]; v[2]=v[1];ix[2]=ix[1]; v[1]=v[0];ix[1]=ix[0]; v[0]=p;ix[0]=m; }
            else                          { v[3]=v[2];ix[3]=ix[2]; v[2]=v[1];ix[2]=ix[1]; v[1]=p;ix[1]=m; }
        } else {
            if (lexgt(p, m, v[2], ix[2])) { v[3]=v[2];ix[3]=ix[2]; v[2]=p;ix[2]=m; }
            else                          { v[3]=p;ix[3]=m; }
        }
    }
}

// ---------------- scratch ----------------
__device__ float  g_xcn[(size_t)B_*CB*N_];   // [B][C][N]
__device__ float  g_xnc[(size_t)B_*N_*CB];   // [B][N][C]
__device__ float4 g_x0nc[(size_t)B_*N_];     // input [B][N][4]
__device__ float  g_xx[(size_t)B_*N_];
__device__ float4 g_cv4[(size_t)B_*N_*S_];
__device__ int4   g_ci4[(size_t)B_*N_*S_];
__device__ int4   g_idx4[(size_t)B_*N_];
__device__ float  g_uv[(size_t)B_*N_*512];   // UV per stage; y5 for conv5
__device__ float  g_mx[(size_t)B_*N_*256];
__device__ float  g_mn[(size_t)B_*N_*256];
__device__ float  g_sum[5*512];
__device__ float  g_ssq[5*512];
__device__ float4 g_wT4[90112];              // packed [c4][O2] per stage

// ---------------- prep: pack weights combined [c4][2O] + clear stats ----------------
__global__ void k_prep_w_all(const float* __restrict__ w1, const float* __restrict__ w2,
                             const float* __restrict__ w3, const float* __restrict__ w4,
                             const float* __restrict__ w5) {
    int t = blockIdx.x*blockDim.x + threadIdx.x;
    if (t < 5*512) { g_sum[t] = 0.f; g_ssq[t] = 0.f; }
    if (t >= 88192) return;
    const float* w; int realC, O, parts, lt;
    if      (t < 128)   { w = w1; realC = 3;   O = 64;  parts = 2; lt = t; }
    else if (t < 2176)  { w = w2; realC = 64;  O = 64;  parts = 2; lt = t - 128; }
    else if (t < 6272)  { w = w3; realC = 64;  O = 128; parts = 2; lt = t - 2176; }
    else if (t < 22656) { w = w4; realC = 128; O = 256; parts = 2; lt = t - 6272; }
    else                { w = w5; realC = 512; O = 512; parts = 1; lt = t - 22656; }
    int O2 = parts * O;
    int o2 = lt % O2; int c4 = lt / O2;
    int part = (o2 >= O) ? 1 : 0; int oc = o2 - part*O;
    float4 v; float* pv = (float*)&v;
    #pragma unroll
    for (int j = 0; j < 4; j++) {
        int c = c4*4 + j;
        pv[j] = (c < realC) ? w[oc*(parts*realC) + part*realC + c] : 0.f;
    }
    g_wT4[t] = v;
}

__global__ void k_prep_x0(const float* __restrict__ x) {
    int t = blockIdx.x*blockDim.x + threadIdx.x;
    if (t >= B_*N_) return;
    int b = t >> 11, n = t & (N_-1);
    float vx = x[(b*3+0)*N_ + n];
    float vy = x[(b*3+1)*N_ + n];
    float vz = x[(b*3+2)*N_ + n];
    g_x0nc[t] = make_float4(vx, vy, vz, 0.f);
    g_xx[t] = vx*vx + vy*vy + vz*vz;
}

// ---------------- knn: distance GEMM with register top-4 (interleaved cols) ----------------
template<int C>
__global__ void __launch_bounds__(256) k_knn3(const float* __restrict__ base, long bstride) {
    constexpr int KCc = (C < 16) ? 4 : 16;
    constexpr int CP = (C + KCc - 1) / KCc * KCc;
    __shared__ float Ash[KCc*TMK];
    __shared__ ull   Bsh[KCc*TNK];
    __shared__ float xxs[TNK];
    const int b  = blockIdx.z;
    const int s  = blockIdx.y;
    const int n0 = blockIdx.x * TMK;
    const float* X = base + (long)b * bstride;
    const float* xxg = g_xx + b*N_;
    const int tid = threadIdx.x;
    const int ty = tid >> 3;   // 0..31 -> 4 rows each
    const int tx = tid & 7;    // 0..7  -> 16 interleaved cols each: {tx, tx+8, ...}
    const int r0 = ty*4;

    float xxr[4];
    #pragma unroll
    for (int i = 0; i < 4; i++) xxr[i] = xxg[n0 + r0 + i];

    float cv[4][4]; int ci[4][4];
    #pragma unroll
    for (int r = 0; r < 4; r++)
        #pragma unroll
        for (int q = 0; q < 4; q++) { cv[r][q] = -3.4e38f; ci[r][q] = 0; }

    for (int mb = 0; mb < (N_/S_)/TNK; mb++) {
        const int m0 = s*(N_/S_) + mb*TNK;
        if (tid < TNK) xxs[tid] = xxg[m0 + tid];
        ull acc0[16], acc1[16];
        #pragma unroll
        for (int j = 0; j < 16; j++) { acc0[j] = 0ull; acc1[j] = 0ull; }

        for (int kc = 0; kc < CP; kc += KCc) {
            #pragma unroll
            for (int t = tid; t < KCc*TMK; t += 256) {
                int c = t >> 7, r = t & (TMK-1);
                Ash[t] = (kc + c < C) ? X[(long)(kc+c)*N_ + n0 + r] : 0.f;
            }
            #pragma unroll
            for (int t = tid; t < KCc*TNK; t += 256) {
                int c = t >> 7, m = t & (TNK-1);
                float v = (kc + c < C) ? X[(long)(kc+c)*N_ + m0 + m] : 0.f;
                Bsh[t] = pack2(v, v);
            }
            __syncthreads();
            #pragma unroll
            for (int cc = 0; cc < KCc; cc++) {
                ulonglong2 aA = *(const ulonglong2*)&Ash[cc*TMK + r0];
                const ull* bp = &Bsh[cc*TNK + tx];
                #pragma unroll
                for (int j = 0; j < 16; j++) {
                    ull bb = bp[j*8];
                    FFMA2(acc0[j], aA.x, bb);
                    FFMA2(acc1[j], aA.y, bb);
                }
            }
            __syncthreads();
        }
        // consume accumulators into register top-4 (column order ascending within thread)
        #pragma unroll
        for (int j = 0; j < 16; j++) {
            float xc = xxs[j*8 + tx];
            int col = m0 + j*8 + tx;
            float2 va = unpack2(acc0[j]);
            ins4(cv[0], ci[0], 2.f*va.x - xxr[0] - xc, col);
            ins4(cv[1], ci[1], 2.f*va.y - xxr[1] - xc, col);
            float2 vb = unpack2(acc1[j]);
            ins4(cv[2], ci[2], 2.f*vb.x - xxr[2] - xc, col);
            ins4(cv[3], ci[3], 2.f*vb.y - xxr[3] - xc, col);
        }
        __syncthreads();
    }
    // butterfly merge across the 8 column-lanes (lex comparator: order-independent)
    #pragma unroll
    for (int st = 1; st <= 4; st <<= 1) {
        #pragma unroll
        for (int r = 0; r < 4; r++) {
            float pv[4]; int pi[4];
            #pragma unroll
            for (int q = 0; q < 4; q++) {
                pv[q] = __shfl_xor_sync(0xffffffffu, cv[r][q], st);
                pi[q] = __shfl_xor_sync(0xffffffffu, ci[r][q], st);
            }
            #pragma unroll
            for (int q = 0; q < 4; q++) ins4lex(cv[r], ci[r], pv[q], pi[q]);
        }
    }
    if (tx == 0) {
        #pragma unroll
        for (int r = 0; r < 4; r++) {
            int o = (b*N_ + n0 + r0 + r)*S_ + s;
            g_cv4[o] = make_float4(cv[r][0], cv[r][1], cv[r][2], cv[r][3]);
            g_ci4[o] = make_int4(ci[r][0], ci[r][1], ci[r][2], ci[r][3]);
        }
    }
}

// ---------------- merge split candidates -> final knn idx ----------------
__global__ void k_merge() {
    int t = blockIdx.x*blockDim.x + threadIdx.x;
    if (t >= B_*N_) return;
    float cv[4] = {-3.4e38f,-3.4e38f,-3.4e38f,-3.4e38f};
    int ci[4] = {0,0,0,0};
    #pragma unroll
    for (int s2 = 0; s2 < S_; s2++) {
        float4 v = g_cv4[t*S_ + s2];
        int4   i = g_ci4[t*S_ + s2];
        ins4lex(cv, ci, v.x, i.x); ins4lex(cv, ci, v.y, i.y);
        ins4lex(cv, ci, v.z, i.z); ins4lex(cv, ci, v.w, i.w);
    }
    g_idx4[t] = make_int4(ci[0], ci[1], ci[2], ci[3]);
}

// ---------------- generic GEMM: out[pt][O2] = src[pt][C] * W[C][O2] (interleaved cols) ----------------
template<int TN>
__global__ void __launch_bounds__(256) k_gemm(const float* __restrict__ src, int CS, int coff,
                                              int C, int c4n, const float4* __restrict__ wb,
                                              int O2, float* __restrict__ out) {
    constexpr int CT = TN/16;
    __shared__ float Ash[16*132];
    __shared__ ull   Bsh[16*TN];
    const int pt0 = blockIdx.x * 128;
    const int ob0 = blockIdx.y * TN;
    const int tid = threadIdx.x;
    const int ty = tid >> 4, tx = tid & 15;
    const int r0 = ty*8;

    ull acc[4][CT];
    #pragma unroll
    for (int p = 0; p < 4; p++)
        #pragma unroll
        for (int j = 0; j < CT; j++) acc[p][j] = 0ull;

    const int C16 = (C + 15) & ~15;
    for (int kc = 0; kc < C16; kc += 16) {
        #pragma unroll
        for (int t = tid; t < 16*128; t += 256) {
            int c = t & 15, r = t >> 4;
            float v = (kc + c < C) ? src[(long)(pt0 + r)*CS + coff + kc + c] : 0.f;
            Ash[c*132 + r] = v;
        }
        #pragma unroll
        for (int t = tid; t < 4*TN; t += 256) {
            int q = t / TN, o = t - q*TN;
            int c4 = (kc >> 2) + q;
            float4 w = (c4 < c4n) ? wb[(long)c4*O2 + ob0 + o] : make_float4(0.f,0.f,0.f,0.f);
            Bsh[(4*q+0)*TN + o] = pack2(w.x, w.x);
            Bsh[(4*q+1)*TN + o] = pack2(w.y, w.y);
            Bsh[(4*q+2)*TN + o] = pack2(w.z, w.z);
            Bsh[(4*q+3)*TN + o] = pack2(w.w, w.w);
        }
        __syncthreads();
        #pragma unroll
        for (int cc = 0; cc < 16; cc++) {
            ulonglong2 aA = *(const ulonglong2*)&Ash[cc*132 + r0];
            ulonglong2 aB = *(const ulonglong2*)&Ash[cc*132 + r0 + 4];
            const ull* bp = &Bsh[cc*TN + tx];
            #pragma unroll
            for (int j = 0; j < CT; j++) {
                ull bb = bp[j*16];
                FFMA2(acc[0][j], aA.x, bb);
                FFMA2(acc[1][j], aA.y, bb);
                FFMA2(acc[2][j], aB.x, bb);
                FFMA2(acc[3][j], aB.y, bb);
            }
        }
        __syncthreads();
    }
    #pragma unroll
    for (int p = 0; p < 4; p++) {
        long rowL = (long)(pt0 + r0 + 2*p) * O2 + ob0 + tx;
        #pragma unroll
        for (int j = 0; j < CT; j++) {
            float2 u = unpack2(acc[p][j]);
            out[rowL + j*16]      = u.x;
            out[rowL + O2 + j*16] = u.y;
        }
    }
}

// ---------------- gather + minmax over k + stats ----------------
__global__ void k_edge_max(const float* __restrict__ uv, int O, int O2, int stage) {
    __shared__ int sidx[PP*K_];
    const int blk = blockIdx.x;
    const int pt0 = blk * PP;
    const int o = threadIdx.x;
    const int b = pt0 >> 11;
    if (o < PP) ((int4*)sidx)[o] = g_idx4[pt0 + o];
    __syncthreads();
    float s1 = 0.f, s2 = 0.f;
    #pragma unroll
    for (int p = 0; p < PP; p++) {
        float v = uv[(long)(pt0 + p)*O2 + O + o];
        float mx = -3.4e38f, mn = 3.4e38f;
        #pragma unroll
        for (int k = 0; k < K_; k++) {
            int nb = sidx[p*K_ + k];
            float u = uv[(long)(b*N_ + nb)*O2 + o];
            float y = u + v;
            mx = fmaxf(mx, y); mn = fminf(mn, y);
            s1 += y; s2 += y*y;
        }
        g_mx[(long)(pt0 + p)*O + o] = mx;
        g_mn[(long)(pt0 + p)*O + o] = mn;
    }
    atomicAdd(&g_sum[stage*512 + o], s1);
    atomicAdd(&g_ssq[stage*512 + o], s2);
}

// ---------------- BN finalize + relu + both layouts + next-stage norms ----------------
__global__ void k_fin_edge(int O, int coff, int stage, const float* __restrict__ gm,
                           const float* __restrict__ bt, float invcnt) {
    __shared__ float red[256];
    const int bn = blockIdx.x;
    const int o  = threadIdx.x;
    const int so = stage*512 + o;
    float mean = g_sum[so] * invcnt;
    float var  = g_ssq[so] * invcnt - mean*mean;
    float a  = gm[o] * rsqrtf(var + 1e-5f);
    float c0 = bt[o] - mean*a;
    long t = (long)bn*O + o;
    float z = (a >= 0.f) ? (a*g_mx[t] + c0) : (a*g_mn[t] + c0);
    z = fmaxf(z, 0.f);
    int b = bn >> 11, n = bn & (N_-1);
    g_xnc[(long)bn*CB + coff + o] = z;
    g_xcn[((long)b*CB + coff + o)*N_ + n] = z;
    red[o] = z*z;
    __syncthreads();
    for (int st = O >> 1; st > 0; st >>= 1) {
        if (o < st) red[o] += red[o + st];
        __syncthreads();
    }
    if (o == 0) g_xx[bn] = red[0];
}

// ---------------- conv5 stats over y5 ----------------
__global__ void __launch_bounds__(512) k_stats5() {
    const int o = threadIdx.x;
    const int p0 = blockIdx.x * 128;
    float s1 = 0.f, s2 = 0.f;
    for (int i = 0; i < 128; i++) {
        float y = g_uv[(long)(p0 + i)*CB + o];
        s1 += y; s2 += y*y;
    }
    atomicAdd(&g_sum[4*512 + o], s1);
    atomicAdd(&g_ssq[4*512 + o], s2);
}

__global__ void k_fin5(const float* __restrict__ gm, const float* __restrict__ bt,
                       float* __restrict__ out) {
    __shared__ float tile[32][33];
    const int b  = blockIdx.z;
    const int o0 = blockIdx.y*32;
    const int n0 = blockIdx.x*32;
    const int tx = threadIdx.x, ty0 = threadIdx.y;
    const float invcnt = 1.f / (float)(B_*N_);
    int o = o0 + tx;
    float mean = g_sum[4*512 + o] * invcnt;
    float var  = g_ssq[4*512 + o] * invcnt - mean*mean;
    float a  = gm[o] * rsqrtf(var + 1e-5f);
    float c0 = bt[o] - mean*a;
    #pragma unroll
    for (int i = 0; i < 4; i++) {
        int ty = ty0 + i*8;
        float y = g_uv[((long)b*N_ + n0 + ty)*CB + o];
        tile[ty][tx] = tanhf(a*y + c0);
    }
    __syncthreads();
    #pragma unroll
    for (int i = 0; i < 4; i++) {
        int ty = ty0 + i*8;
        out[((long)b*CB + o0 + ty)*N_ + n0 + tx] = tile[tx][ty];
    }
}

// ---------------- launch ----------------
extern "C" void kernel_launch(void* const* d_in, const int* in_sizes, int n_in,
                              void* d_out, int out_size) {
    const float* x = (const float*)d_in[0];
    const float* W[5]; const float* G[5]; const float* Bt[5];
    for (int i = 0; i < 5; i++) {
        W[i]  = (const float*)d_in[1 + 3*i];
        G[i]  = (const float*)d_in[2 + 3*i];
        Bt[i] = (const float*)d_in[3 + 3*i];
    }
    float* out = (float*)d_out;

    float* xcn;   cudaGetSymbolAddress((void**)&xcn,  g_xcn);
    float* xnc;   cudaGetSymbolAddress((void**)&xnc,  g_xnc);
    float* x0nc;  cudaGetSymbolAddress((void**)&x0nc, g_x0nc);
    float* uv;    cudaGetSymbolAddress((void**)&uv,   g_uv);
    float4* wt;   cudaGetSymbolAddress((void**)&wt,   g_wT4);

    const float invE = 1.f / (float)(B_*N_*K_);
    const dim3 kg(N_/TMK, S_, B_);
    const int wstart[5] = {0, 128, 2176, 6272, 22656};

    k_prep_w_all<<<(88192 + 255)/256, 256>>>(W[0], W[1], W[2], W[3], W[4]);
    k_prep_x0<<<(B_*N_ + 255)/256, 256>>>(x);

    // stage 0: C=3 -> O=64
    k_knn3<3><<<kg, 256>>>(x, (long)3*N_);
    k_merge<<<B_*N_/256, 256>>>();
    k_gemm<64><<<dim3(128, 2), 256>>>(x0nc, 4, 0, 4, 1, wt + wstart[0], 128, uv);
    k_edge_max<<<B_*N_/PP, 64>>>(uv, 64, 128, 0);
    k_fin_edge<<<B_*N_, 64>>>(64, 0, 0, G[0], Bt[0], invE);
    // stage 1: C=64 -> O=64
    k_knn3<64><<<kg, 256>>>(xcn, (long)CB*N_);
    k_merge<<<B_*N_/256, 256>>>();
    k_gemm<64><<<dim3(128, 2), 256>>>(xnc, CB, 0, 64, 16, wt + wstart[1], 128, uv);
    k_edge_max<<<B_*N_/PP, 64>>>(uv, 64, 128, 1);
    k_fin_edge<<<B_*N_, 64>>>(64, 64, 1, G[1], Bt[1], invE);
    // stage 2: C=64 -> O=128
    k_knn3<64><<<kg, 256>>>(xcn + (long)64*N_, (long)CB*N_);
    k_merge<<<B_*N_/256, 256>>>();
    k_gemm<128><<<dim3(128, 2), 256>>>(xnc, CB, 64, 64, 16, wt + wstart[2], 256, uv);
    k_edge_max<<<B_*N_/PP, 128>>>(uv, 128, 256, 2);
    k_fin_edge<<<B_*N_, 128>>>(128, 128, 2, G[2], Bt[2], invE);
    // stage 3: C=128 -> O=256
    k_knn3<128><<<kg, 256>>>(xcn + (long)128*N_, (long)CB*N_);
    k_merge<<<B_*N_/256, 256>>>();
    k_gemm<128><<<dim3(128, 4), 256>>>(xnc, CB, 128, 128, 32, wt + wstart[3], 512, uv);
    k_edge_max<<<B_*N_/PP, 256>>>(uv, 256, 512, 3);
    k_fin_edge<<<B_*N_, 256>>>(256, 256, 3, G[3], Bt[3], invE);
    // block 5: 512x512
    k_gemm<128><<<dim3(128, 4), 256>>>(xnc, CB, 0, 512, 128, wt + wstart[4], 512, uv);
    k_stats5<<<128, 512>>>();
    k_fin5<<<dim3(N_/32, CB/32, B_), dim3(32, 8)>>>(G[4], Bt[4], out);
}

// round 5
// speedup vs baseline: 4.0203x; 1.0560x over previous
#include <cuda_runtime.h>
#include <math.h>

#define B_ 8
#define N_ 2048
#define K_ 4
#define CB 512
#define PP 8
#define TMK 128
#define TNK 128

typedef unsigned long long ull;

#define FFMA2(d,a,b) asm("fma.rn.f32x2 %0, %1, %2, %0;" : "+l"(d) : "l"(a), "l"(b))
__device__ __forceinline__ ull pack2(float lo, float hi) {
    ull r; asm("mov.b64 %0, {%1,%2};" : "=l"(r) : "f"(lo), "f"(hi)); return r;
}
__device__ __forceinline__ float2 unpack2(ull v) {
    float2 f; asm("mov.b64 {%0,%1}, %2;" : "=f"(f.x), "=f"(f.y) : "l"(v)); return f;
}

// top-4 insertion, strict > (stable: earlier-inserted wins ties)
__device__ __forceinline__ void ins4(float (&v)[4], int (&ix)[4], float p, int m) {
    if (p > v[3]) {
        if (p > v[1]) {
            if (p > v[0]) { v[3]=v[2];ix[3]=ix[2]; v[2]=v[1];ix[2]=ix[1]; v[1]=v[0];ix[1]=ix[0]; v[0]=p;ix[0]=m; }
            else          { v[3]=v[2];ix[3]=ix[2]; v[2]=v[1];ix[2]=ix[1]; v[1]=p;ix[1]=m; }
        } else {
            if (p > v[2]) { v[3]=v[2];ix[3]=ix[2]; v[2]=p;ix[2]=m; }
            else          { v[3]=p;ix[3]=m; }
        }
    }
}
__device__ __forceinline__ bool lexgt(float pv, int pi, float qv, int qi) {
    return (pv > qv) || (pv == qv && pi < qi);
}
__device__ __forceinline__ void ins4lex(float (&v)[4], int (&ix)[4], float p, int m) {
    if (lexgt(p, m, v[3], ix[3])) {
        if (lexgt(p, m, v[1], ix[1])) {
            if (lexgt(p, m, v[0], ix[0])) { v[3]=v[2];ix[3]=ix[2]; v[2]=v[1];ix[2]=ix[1]; v[1]=v[0];ix[1]=ix[0]; v[0]=p;ix[0]=m; }
            else                          { v[3]=v[2];ix[3]=ix[2]; v[2]=v[1];ix[2]=ix[1]; v[1]=p;ix[1]=m; }
        } else {
            if (lexgt(p, m, v[2], ix[2])) { v[3]=v[2];ix[3]=ix[2]; v[2]=p;ix[2]=m; }
            else                          { v[3]=p;ix[3]=m; }
        }
    }
}

// ---------------- scratch ----------------
__device__ float  g_xcn[(size_t)B_*CB*N_];   // [B][C][N]
__device__ float  g_xnc[(size_t)B_*N_*CB];   // [B][N][C]
__device__ float4 g_x0nc[(size_t)B_*N_];     // input [B][N][4]
__device__ float  g_xx[(size_t)B_*N_];
__device__ int4   g_idx4[(size_t)B_*N_];
__device__ float  g_uv[(size_t)B_*N_*512];   // UV per stage; y5 for conv5
__device__ float  g_mx[(size_t)B_*N_*256];
__device__ float  g_mn[(size_t)B_*N_*256];
__device__ float  g_sum[5*512];
__device__ float  g_ssq[5*512];
__device__ float4 g_wT4[90112];              // packed [c4][O2] per stage

// ---------------- prep: pack weights combined [c4][2O] + clear stats ----------------
__global__ void k_prep_w_all(const float* __restrict__ w1, const float* __restrict__ w2,
                             const float* __restrict__ w3, const float* __restrict__ w4,
                             const float* __restrict__ w5) {
    int t = blockIdx.x*blockDim.x + threadIdx.x;
    if (t < 5*512) { g_sum[t] = 0.f; g_ssq[t] = 0.f; }
    if (t >= 88192) return;
    const float* w; int realC, O, parts, lt;
    if      (t < 128)   { w = w1; realC = 3;   O = 64;  parts = 2; lt = t; }
    else if (t < 2176)  { w = w2; realC = 64;  O = 64;  parts = 2; lt = t - 128; }
    else if (t < 6272)  { w = w3; realC = 64;  O = 128; parts = 2; lt = t - 2176; }
    else if (t < 22656) { w = w4; realC = 128; O = 256; parts = 2; lt = t - 6272; }
    else                { w = w5; realC = 512; O = 512; parts = 1; lt = t - 22656; }
    int O2 = parts * O;
    int o2 = lt % O2; int c4 = lt / O2;
    int part = (o2 >= O) ? 1 : 0; int oc = o2 - part*O;
    float4 v; float* pv = (float*)&v;
    #pragma unroll
    for (int j = 0; j < 4; j++) {
        int c = c4*4 + j;
        pv[j] = (c < realC) ? w[oc*(parts*realC) + part*realC + c] : 0.f;
    }
    g_wT4[t] = v;
}

__global__ void k_prep_x0(const float* __restrict__ x) {
    int t = blockIdx.x*blockDim.x + threadIdx.x;
    if (t >= B_*N_) return;
    int b = t >> 11, n = t & (N_-1);
    float vx = x[(b*3+0)*N_ + n];
    float vy = x[(b*3+1)*N_ + n];
    float vz = x[(b*3+2)*N_ + n];
    g_x0nc[t] = make_float4(vx, vy, vz, 0.f);
    g_xx[t] = vx*vx + vy*vy + vz*vz;
}

// ---------------- knn: A resident, B double-buffered, register top-4 ----------------
template<int C>
__global__ void __launch_bounds__(256) k_knn(const float* __restrict__ base, long bstride) {
    constexpr int KCc = (C < 16) ? 4 : 16;
    constexpr int NCH = (C + KCc - 1)/KCc;
    constexpr int CP  = NCH*KCc;
    constexpr int NG  = (N_/TNK)*NCH;
    extern __shared__ char smraw[];
    float* Ash = (float*)smraw;                                   // [CP][TMK]
    ull*   Bsh = (ull*)(smraw + (size_t)CP*TMK*4);                // [2][KCc][TNK]
    float* xxs = (float*)(smraw + (size_t)CP*TMK*4 + 2*KCc*TNK*8);// [2][TNK]
    const int b  = blockIdx.y;
    const int n0 = blockIdx.x * TMK;
    const float* X = base + (long)b*bstride;
    const float* xxg = g_xx + b*N_;
    const int tid = threadIdx.x;
    const int ty = tid >> 3, tx = tid & 7;
    const int r0 = ty*4;

    // full A panel, loaded once
    #pragma unroll
    for (int t = tid; t < CP*TMK; t += 256) {
        int c = t >> 7, r = t & 127;
        Ash[t] = (c < C) ? X[(long)c*N_ + n0 + r] : 0.f;
    }
    float xxr[4];
    #pragma unroll
    for (int i = 0; i < 4; i++) xxr[i] = xxg[n0 + r0 + i];

    float cv[4][4]; int ci[4][4];
    #pragma unroll
    for (int r = 0; r < 4; r++)
        #pragma unroll
        for (int q = 0; q < 4; q++) { cv[r][q] = -3.4e38f; ci[r][q] = 0; }

    // initial B chunk (g=0: mb=0, ch=0)
    #pragma unroll
    for (int t = tid; t < KCc*TNK; t += 256) {
        int c = t >> 7, m = t & 127;
        float v = (c < C) ? X[(long)c*N_ + m] : 0.f;
        Bsh[t] = pack2(v, v);
    }
    if (tid < TNK) xxs[tid] = xxg[tid];
    __syncthreads();

    ull acc0[16], acc1[16];
    #pragma unroll
    for (int j = 0; j < 16; j++) { acc0[j] = 0ull; acc1[j] = 0ull; }

    for (int g = 0; g < NG; g++) {
        const int mb = g / NCH, ch = g - mb*NCH;
        // prefetch chunk g+1 into other buffer
        if (g + 1 < NG) {
            const int mb1 = (g+1)/NCH, ch1 = (g+1) - mb1*NCH;
            const int m01 = mb1*TNK;
            ull* bd = Bsh + ((g+1)&1)*(KCc*TNK);
            #pragma unroll
            for (int t = tid; t < KCc*TNK; t += 256) {
                int c = t >> 7, m = t & 127;
                int cg = ch1*KCc + c;
                float v = (cg < C) ? X[(long)cg*N_ + m01 + m] : 0.f;
                bd[t] = pack2(v, v);
            }
            if (ch1 == 0 && tid < TNK) xxs[(mb1&1)*TNK + tid] = xxg[m01 + tid];
        }
        // compute chunk g
        const ull* bb0 = Bsh + (g&1)*(KCc*TNK);
        #pragma unroll
        for (int cc = 0; cc < KCc; cc++) {
            ulonglong2 aA = *(const ulonglong2*)&Ash[(ch*KCc + cc)*TMK + r0];
            const ull* bp = bb0 + cc*TNK + tx;
            #pragma unroll
            for (int j = 0; j < 16; j++) {
                ull bbv = bp[j*8];
                FFMA2(acc0[j], aA.x, bbv);
                FFMA2(acc1[j], aA.y, bbv);
            }
        }
        if (ch == NCH - 1) {
            const float* xxb = xxs + (mb&1)*TNK;
            const int m0 = mb*TNK;
            #pragma unroll
            for (int j = 0; j < 16; j++) {
                float xc = xxb[j*8 + tx];
                int col = m0 + j*8 + tx;
                float2 va = unpack2(acc0[j]);
                ins4(cv[0], ci[0], 2.f*va.x - xxr[0] - xc, col);
                ins4(cv[1], ci[1], 2.f*va.y - xxr[1] - xc, col);
                float2 vb = unpack2(acc1[j]);
                ins4(cv[2], ci[2], 2.f*vb.x - xxr[2] - xc, col);
                ins4(cv[3], ci[3], 2.f*vb.y - xxr[3] - xc, col);
                acc0[j] = 0ull; acc1[j] = 0ull;
            }
        }
        __syncthreads();
    }
    // butterfly merge across the 8 column-lanes (lex: order-independent)
    #pragma unroll
    for (int st = 1; st <= 4; st <<= 1) {
        #pragma unroll
        for (int r = 0; r < 4; r++) {
            float pv[4]; int pi[4];
            #pragma unroll
            for (int q = 0; q < 4; q++) {
                pv[q] = __shfl_xor_sync(0xffffffffu, cv[r][q], st);
                pi[q] = __shfl_xor_sync(0xffffffffu, ci[r][q], st);
            }
            #pragma unroll
            for (int q = 0; q < 4; q++) ins4lex(cv[r], ci[r], pv[q], pi[q]);
        }
    }
    if (tx == 0) {
        #pragma unroll
        for (int r = 0; r < 4; r++)
            g_idx4[b*N_ + n0 + r0 + r] = make_int4(ci[r][0], ci[r][1], ci[r][2], ci[r][3]);
    }
}

// ---------------- generic GEMM: out[pt][O2] = src[pt][C] * W[C][O2] ----------------
template<int TN>
__global__ void __launch_bounds__(256) k_gemm(const float* __restrict__ src, int CS, int coff,
                                              int C, int c4n, const float4* __restrict__ wb,
                                              int O2, float* __restrict__ out) {
    constexpr int CT = TN/16;
    __shared__ float Ash[16*132];
    __shared__ ull   Bsh[16*TN];
    const int pt0 = blockIdx.x * 128;
    const int ob0 = blockIdx.y * TN;
    const int tid = threadIdx.x;
    const int ty = tid >> 4, tx = tid & 15;
    const int r0 = ty*8;

    ull acc[4][CT];
    #pragma unroll
    for (int p = 0; p < 4; p++)
        #pragma unroll
        for (int j = 0; j < CT; j++) acc[p][j] = 0ull;

    const int C16 = (C + 15) & ~15;
    for (int kc = 0; kc < C16; kc += 16) {
        #pragma unroll
        for (int t = tid; t < 16*128; t += 256) {
            int c = t & 15, r = t >> 4;
            float v = (kc + c < C) ? src[(long)(pt0 + r)*CS + coff + kc + c] : 0.f;
            Ash[c*132 + r] = v;
        }
        #pragma unroll
        for (int t = tid; t < 4*TN; t += 256) {
            int q = t / TN, o = t - q*TN;
            int c4 = (kc >> 2) + q;
            float4 w = (c4 < c4n) ? wb[(long)c4*O2 + ob0 + o] : make_float4(0.f,0.f,0.f,0.f);
            Bsh[(4*q+0)*TN + o] = pack2(w.x, w.x);
            Bsh[(4*q+1)*TN + o] = pack2(w.y, w.y);
            Bsh[(4*q+2)*TN + o] = pack2(w.z, w.z);
            Bsh[(4*q+3)*TN + o] = pack2(w.w, w.w);
        }
        __syncthreads();
        #pragma unroll
        for (int cc = 0; cc < 16; cc++) {
            ulonglong2 aA = *(const ulonglong2*)&Ash[cc*132 + r0];
            ulonglong2 aB = *(const ulonglong2*)&Ash[cc*132 + r0 + 4];
            const ull* bp = &Bsh[cc*TN + tx];
            #pragma unroll
            for (int j = 0; j < CT; j++) {
                ull bb = bp[j*16];
                FFMA2(acc[0][j], aA.x, bb);
                FFMA2(acc[1][j], aA.y, bb);
                FFMA2(acc[2][j], aB.x, bb);
                FFMA2(acc[3][j], aB.y, bb);
            }
        }
        __syncthreads();
    }
    #pragma unroll
    for (int p = 0; p < 4; p++) {
        long rowL = (long)(pt0 + r0 + 2*p) * O2 + ob0 + tx;
        #pragma unroll
        for (int j = 0; j < CT; j++) {
            float2 u = unpack2(acc[p][j]);
            out[rowL + j*16]      = u.x;
            out[rowL + O2 + j*16] = u.y;
        }
    }
}

// ---------------- gather + minmax over k + stats ----------------
__global__ void k_edge_max(const float* __restrict__ uv, int O, int O2, int stage) {
    __shared__ int sidx[PP*K_];
    const int blk = blockIdx.x;
    const int pt0 = blk * PP;
    const int o = threadIdx.x;
    const int b = pt0 >> 11;
    if (o < PP) ((int4*)sidx)[o] = g_idx4[pt0 + o];
    __syncthreads();
    float s1 = 0.f, s2 = 0.f;
    #pragma unroll
    for (int p = 0; p < PP; p++) {
        float v = uv[(long)(pt0 + p)*O2 + O + o];
        float mx = -3.4e38f, mn = 3.4e38f;
        #pragma unroll
        for (int k = 0; k < K_; k++) {
            int nb = sidx[p*K_ + k];
            float u = uv[(long)(b*N_ + nb)*O2 + o];
            float y = u + v;
            mx = fmaxf(mx, y); mn = fminf(mn, y);
            s1 += y; s2 += y*y;
        }
        g_mx[(long)(pt0 + p)*O + o] = mx;
        g_mn[(long)(pt0 + p)*O + o] = mn;
    }
    atomicAdd(&g_sum[stage*512 + o], s1);
    atomicAdd(&g_ssq[stage*512 + o], s2);
}

// ---------------- BN finalize + relu + both layouts + next-stage norms ----------------
__global__ void k_fin_edge(int O, int coff, int stage, const float* __restrict__ gm,
                           const float* __restrict__ bt, float invcnt) {
    __shared__ float wsum[8];
    const int bn = blockIdx.x;
    const int o  = threadIdx.x;
    const int so = stage*512 + o;
    float mean = g_sum[so] * invcnt;
    float var  = g_ssq[so] * invcnt - mean*mean;
    float a  = gm[o] * rsqrtf(var + 1e-5f);
    float c0 = bt[o] - mean*a;
    long t = (long)bn*O + o;
    float z = (a >= 0.f) ? (a*g_mx[t] + c0) : (a*g_mn[t] + c0);
    z = fmaxf(z, 0.f);
    int b = bn >> 11, n = bn & (N_-1);
    g_xnc[(long)bn*CB + coff + o] = z;
    g_xcn[((long)b*CB + coff + o)*N_ + n] = z;
    float r = z*z;
    #pragma unroll
    for (int d = 16; d; d >>= 1) r += __shfl_xor_sync(0xffffffffu, r, d);
    if ((o & 31) == 0) wsum[o >> 5] = r;
    __syncthreads();
    if (o == 0) {
        float s = 0.f;
        #pragma unroll
        for (int w = 0; w < 8; w++) if (w < (O >> 5)) s += wsum[w];
        g_xx[bn] = s;
    }
}

// ---------------- conv5 stats over y5 ----------------
__global__ void __launch_bounds__(512) k_stats5() {
    const int o = threadIdx.x;
    const int p0 = blockIdx.x * 128;
    float s1 = 0.f, s2 = 0.f;
    for (int i = 0; i < 128; i++) {
        float y = g_uv[(long)(p0 + i)*CB + o];
        s1 += y; s2 += y*y;
    }
    atomicAdd(&g_sum[4*512 + o], s1);
    atomicAdd(&g_ssq[4*512 + o], s2);
}

__global__ void k_fin5(const float* __restrict__ gm, const float* __restrict__ bt,
                       float* __restrict__ out) {
    __shared__ float tile[32][33];
    const int b  = blockIdx.z;
    const int o0 = blockIdx.y*32;
    const int n0 = blockIdx.x*32;
    const int tx = threadIdx.x, ty0 = threadIdx.y;
    const float invcnt = 1.f / (float)(B_*N_);
    int o = o0 + tx;
    float mean = g_sum[4*512 + o] * invcnt;
    float var  = g_ssq[4*512 + o] * invcnt - mean*mean;
    float a  = gm[o] * rsqrtf(var + 1e-5f);
    float c0 = bt[o] - mean*a;
    #pragma unroll
    for (int i = 0; i < 4; i++) {
        int ty = ty0 + i*8;
        float y = g_uv[((long)b*N_ + n0 + ty)*CB + o];
        tile[ty][tx] = tanhf(a*y + c0);
    }
    __syncthreads();
    #pragma unroll
    for (int i = 0; i < 4; i++) {
        int ty = ty0 + i*8;
        out[((long)b*CB + o0 + ty)*N_ + n0 + tx] = tile[tx][ty];
    }
}

// ---------------- launch ----------------
extern "C" void kernel_launch(void* const* d_in, const int* in_sizes, int n_in,
                              void* d_out, int out_size) {
    const float* x = (const float*)d_in[0];
    const float* W[5]; const float* G[5]; const float* Bt[5];
    for (int i = 0; i < 5; i++) {
        W[i]  = (const float*)d_in[1 + 3*i];
        G[i]  = (const float*)d_in[2 + 3*i];
        Bt[i] = (const float*)d_in[3 + 3*i];
    }
    float* out = (float*)d_out;

    float* xcn;   cudaGetSymbolAddress((void**)&xcn,  g_xcn);
    float* xnc;   cudaGetSymbolAddress((void**)&xnc,  g_xnc);
    float* x0nc;  cudaGetSymbolAddress((void**)&x0nc, g_x0nc);
    float* uv;    cudaGetSymbolAddress((void**)&uv,   g_uv);
    float4* wt;   cudaGetSymbolAddress((void**)&wt,   g_wT4);

    const int SMK3   = 4*TMK*4   + 2*4*TNK*8  + 2*TNK*4;   // 11264
    const int SMK64  = 64*TMK*4  + 2*16*TNK*8 + 2*TNK*4;   // 66560
    const int SMK128 = 128*TMK*4 + 2*16*TNK*8 + 2*TNK*4;   // 99328
    cudaFuncSetAttribute(k_knn<3>,   cudaFuncAttributeMaxDynamicSharedMemorySize, SMK3);
    cudaFuncSetAttribute(k_knn<64>,  cudaFuncAttributeMaxDynamicSharedMemorySize, SMK64);
    cudaFuncSetAttribute(k_knn<128>, cudaFuncAttributeMaxDynamicSharedMemorySize, SMK128);

    const float invE = 1.f / (float)(B_*N_*K_);
    const dim3 kg(N_/TMK, B_);
    const int wstart[5] = {0, 128, 2176, 6272, 22656};

    // stage 0 (ordered so launch idx 3 = k_knn<3> for the profiler slot)
    k_prep_w_all<<<(88192 + 255)/256, 256>>>(W[0], W[1], W[2], W[3], W[4]);
    k_prep_x0<<<(B_*N_ + 255)/256, 256>>>(x);
    k_gemm<64><<<dim3(128, 2), 256>>>(x0nc, 4, 0, 4, 1, wt + wstart[0], 128, uv);
    k_knn<3><<<kg, 256, SMK3>>>(x, (long)3*N_);
    k_edge_max<<<B_*N_/PP, 64>>>(uv, 64, 128, 0);
    k_fin_edge<<<B_*N_, 64>>>(64, 0, 0, G[0], Bt[0], invE);
    // stage 1: C=64 -> O=64
    k_knn<64><<<kg, 256, SMK64>>>(xcn, (long)CB*N_);
    k_gemm<64><<<dim3(128, 2), 256>>>(xnc, CB, 0, 64, 16, wt + wstart[1], 128, uv);
    k_edge_max<<<B_*N_/PP, 64>>>(uv, 64, 128, 1);
    k_fin_edge<<<B_*N_, 64>>>(64, 64, 1, G[1], Bt[1], invE);
    // stage 2: C=64 -> O=128
    k_knn<64><<<kg, 256, SMK64>>>(xcn + (long)64*N_, (long)CB*N_);
    k_gemm<128><<<dim3(128, 2), 256>>>(xnc, CB, 64, 64, 16, wt + wstart[2], 256, uv);
    k_edge_max<<<B_*N_/PP, 128>>>(uv, 128, 256, 2);
    k_fin_edge<<<B_*N_, 128>>>(128, 128, 2, G[2], Bt[2], invE);
    // stage 3: C=128 -> O=256
    k_knn<128><<<kg, 256, SMK128>>>(xcn + (long)128*N_, (long)CB*N_);
    k_gemm<128><<<dim3(128, 4), 256>>>(xnc, CB, 128, 128, 32, wt + wstart[3], 512, uv);
    k_edge_max<<<B_*N_/PP, 256>>>(uv, 256, 512, 3);
    k_fin_edge<<<B_*N_, 256>>>(256, 256, 3, G[3], Bt[3], invE);
    // block 5: 512x512
    k_gemm<128><<<dim3(128, 4), 256>>>(xnc, CB, 0, 512, 128, wt + wstart[4], 512, uv);
    k_stats5<<<128, 512>>>();
    k_fin5<<<dim3(N_/32, CB/32, B_), dim3(32, 8)>>>(G[4], Bt[4], out);
}